// round 1
// baseline (speedup 1.0000x reference)
#include <cuda_runtime.h>

#define KN   50
#define MBN  10
#define BPC  16              // batches per CTA
#define NTHR (BPC*MBN)       // 160 threads

typedef unsigned long long u64;

__device__ __forceinline__ u64 fma2(u64 a, u64 b, u64 c){
    u64 d; asm("fma.rn.f32x2 %0, %1, %2, %3;" : "=l"(d) : "l"(a), "l"(b), "l"(c)); return d;
}
__device__ __forceinline__ u64 packs(float x){
    u64 r; asm("mov.b64 %0, {%1, %1};" : "=l"(r) : "f"(x)); return r;
}
__device__ __forceinline__ u64 packp(float lo, float hi){
    u64 r; asm("mov.b64 %0, {%1, %2};" : "=l"(r) : "f"(lo), "f"(hi)); return r;
}
__device__ __forceinline__ void unpk(u64 v, float& lo, float& hi){
    asm("mov.b64 {%0, %1}, %2;" : "=f"(lo), "=f"(hi) : "l"(v));
}

struct __align__(16) Sh {
    float kcb[2][BPC][52];   // kc_n staging, double buffered (52 = 13*16B rows)
    float lkb[2][BPC][52];   // low_kc_n staging
    float psum[BPC][12];     // APL partial sums
    float dan[2][BPC][12];   // dan state, double buffered
    float mbon[BPC][12];     // mbon_n exchange
    float WdmT[10][12];      // [m][d] = mbon_dan_weight[d,m]
    float WddT[10][12];      // [d][j] = dan_dan_weight[j,d]
    float WmdT[10][12];      // [d][m'] = dan_mbon_weight[m',d]
    float dec[2][12];        // dec_W rows
    float decb[2];
};

__device__ __forceinline__ void load10(const float* p, float* o){
    float4 a = *(const float4*)p;
    float4 b = *(const float4*)(p+4);
    float2 c = *(const float2*)(p+8);
    o[0]=a.x; o[1]=a.y; o[2]=a.z; o[3]=a.w;
    o[4]=b.x; o[5]=b.y; o[6]=b.z; o[7]=b.w;
    o[8]=c.x; o[9]=c.y;
}

__global__ void __launch_bounds__(NTHR, 2) fly_kernel(
    const float* __restrict__ odor,  const float* __restrict__ ctx,
    const float* __restrict__ pn_w,  const float* __restrict__ kn_b,
    const float* __restrict__ apl_w, const float* __restrict__ apl_b,
    const float* __restrict__ Wdm,   const float* __restrict__ mb_b,
    const float* __restrict__ Wmd,   const float* __restrict__ Wdd,
    const float* __restrict__ Wcd,   const float* __restrict__ dan_b,
    const float* __restrict__ decW,  const float* __restrict__ decB,
    const float* __restrict__ kw0,   const float* __restrict__ wa0,
    float* __restrict__ out, int Bn, int T)
{
    __shared__ Sh sh;
    const int tid = threadIdx.x;
    const int m   = tid % MBN;        // owned MBON/DAN column
    const int bl  = tid / MBN;        // batch within CTA
    const int b   = blockIdx.x * BPC + bl;
    const int k0  = m * 5;            // owned KC rows k0..k0+4

    // ---- shared init: zero dan buffers, stage transposed small weights ----
    for (int i = tid; i < 2*BPC*12; i += NTHR) (&sh.dan[0][0][0])[i] = 0.f;
    if (tid < 100) {
        int d = tid / 10, j = tid % 10;
        sh.WdmT[j][d] = Wdm[d*10 + j];   // column m of mbon_dan
        sh.WddT[d][j] = Wdd[j*10 + d];   // column d of dan_dan
        sh.WmdT[d][j] = Wmd[j*10 + d];   // column d of dan_mbon
    }
    if (tid < 20) sh.dec[tid/10][tid%10] = decW[tid];
    if (tid < 2)  sh.decb[tid] = decB[tid];

    // ---- per-thread constants ----
    float pw0[5], pw1[5], pw2[5], kb[5], aw[5];
    {
        const float* pwp = pn_w + (size_t)b*150 + k0;
        #pragma unroll
        for (int j = 0; j < 5; j++) {
            pw0[j] = pwp[j]; pw1[j] = pwp[50+j]; pw2[j] = pwp[100+j];
            kb[j]  = kn_b[k0+j]; aw[j] = apl_w[k0+j];
        }
    }
    const float aplB = apl_b[0];
    const float mbB  = mb_b[m];
    const float wcm  = Wcd[m];
    const float dBm  = dan_b[m];

    // ---- plastic state in registers, packed as f32x2 pairs (k, k+1) ----
    // wac holds 0.25*wact  (so kc_w update is one fma2, and syn scale folds)
    u64 kcw[25], wac[25];
    {
        const float* kp = kw0 + (size_t)b*500 + m;   // stride 10 over k
        const float* ap = wa0 + (size_t)b*500 + m;
        #pragma unroll
        for (int i = 0; i < 25; i++) {
            kcw[i] = packp(kp[20*i], kp[20*i + 10]);
            wac[i] = packp(0.25f*ap[20*i], 0.25f*ap[20*i + 10]);
        }
    }
    __syncthreads();

    float wdm[10];
    load10(&sh.WdmT[m][0], wdm);

    // ---- per-thread recurrent state ----
    float kcs[5] = {0,0,0,0,0};     // kc[k0..k0+4]
    float lks[5] = {0,0,0,0,0};     // low_kc[k0..k0+4]
    float apl = 0.f, mbon = 0.f, danm = 0.f, lowdan = 0.f;

    const float ALPHA = 0.5f/5.5f;
    const float OMA   = 1.0f - 0.5f/5.5f;
    const u64   C75   = packs(0.75f);

    const float* odp = odor + (size_t)b*3;
    const float* ctp = ctx  + b;
    float*       otp = out  + (size_t)b*2 + m;
    const size_t odS = (size_t)Bn*3, ctS = (size_t)Bn, otS = (size_t)Bn*2;

    for (int t = 0; t < T; t++) {
        const int wr = t & 1;
        const int rd = wr ^ 1;   // dan buffer written last step

        // ================= Phase A: Kenyon + low-pass (own 5 k's) =========
        float o0 = odp[0], o1 = odp[1], o2 = odp[2];
        float cx = ctp[0];
        float psum = 0.f;
        #pragma unroll
        for (int j = 0; j < 5; j++) {
            float pn  = fmaf(o0, pw0[j], fmaf(o1, pw1[j], o2*pw2[j]));
            float r   = fmaxf(pn - apl + kb[j], 0.f);
            float kcn = 0.5f*kcs[j] + 0.5f*r;
            kcs[j] = kcn;
            sh.kcb[wr][bl][k0+j] = kcn;
            float lkn = fmaf(ALPHA, kcn, OMA*lks[j]);
            lks[j] = lkn;
            sh.lkb[wr][bl][k0+j] = lkn;
            psum = fmaf(kcn, aw[j], psum);
        }
        sh.psum[bl][m] = psum;
        __syncthreads();                       // BAR1

        // ================= Phase B: APL, dan_mod, kcv + kc_w decay ========
        {
            float ps[10]; load10(&sh.psum[bl][0], ps);
            float s = ((ps[0]+ps[1]) + (ps[2]+ps[3]))
                    + (((ps[4]+ps[5]) + (ps[6]+ps[7])) + (ps[8]+ps[9]));
            apl = 0.5f*apl + 0.5f*fmaxf(s + aplB, 0.f);
        }
        float dmod;
        {
            float dj[10]; load10(&sh.dan[rd][bl][0], dj);
            float acc = 0.f;
            #pragma unroll
            for (int d = 0; d < 10; d++) acc = fmaf(dj[d], wdm[d], acc);
            dmod = 1.f/(1.f + __expf(-acc));
        }
        // kcv = kc_n . kc_w (old);  kc_w <- 0.75*kc_w + wac (= 0.25*wact old)
        u64 acc0 = 0ull, acc1 = 0ull;
        {
            const ulonglong2* kp2 = (const ulonglong2*)&sh.kcb[wr][bl][0];
            #pragma unroll
            for (int i = 0; i < 12; i++) {
                ulonglong2 v = kp2[i];
                acc0 = fma2(v.x, kcw[2*i],   acc0);
                acc1 = fma2(v.y, kcw[2*i+1], acc1);
                kcw[2*i]   = fma2(kcw[2*i],   C75, wac[2*i]);
                kcw[2*i+1] = fma2(kcw[2*i+1], C75, wac[2*i+1]);
            }
            u64 v = *(const u64*)&sh.kcb[wr][bl][48];
            acc0 = fma2(v, kcw[24], acc0);
            kcw[24] = fma2(kcw[24], C75, wac[24]);
        }
        float l0,h0,l1,h1; unpk(acc0,l0,h0); unpk(acc1,l1,h1);
        float kcv = (l0+h0) + (l1+h1);
        mbon = 0.5f*mbon + 0.5f*dmod*fmaxf(kcv + mbB, 0.f);
        sh.mbon[bl][m] = mbon;
        __syncthreads();                       // BAR2

        // ================= Phase C: DAN update, decoder output ============
        float mb[10]; load10(&sh.mbon[bl][0], mb);
        {
            float dj[10];  load10(&sh.dan[rd][bl][0], dj);
            float wdd[10]; load10(&sh.WddT[m][0], wdd);
            float wmd[10]; load10(&sh.WmdT[m][0], wmd);
            float dp = fmaf(cx, wcm, dBm);
            #pragma unroll
            for (int j = 0; j < 10; j++) dp = fmaf(dj[j], wdd[j], dp);
            #pragma unroll
            for (int j = 0; j < 10; j++) dp = fmaf(mb[j], wmd[j], dp);
            danm = 0.5f*danm + 0.5f*fmaxf(dp, 0.f);
        }
        sh.dan[wr][bl][m] = danm;
        lowdan = fmaf(ALPHA, danm, OMA*lowdan);
        if (m < 2) {
            float dw[10]; load10(&sh.dec[m][0], dw);
            float o = sh.decb[m];
            #pragma unroll
            for (int j = 0; j < 10; j++) o = fmaf(mb[j], dw[j], o);
            otp[0] = o;
        }

        // ================= Loop 2: plasticity (wact update) ===============
        // wac += 0.125*lowdan_n * kc_n  -  0.125*dan_n * low_kc_n
        {
            u64 cA = packs( 0.125f*lowdan);
            u64 cB = packs(-0.125f*danm);
            const ulonglong2* kp2 = (const ulonglong2*)&sh.kcb[wr][bl][0];
            const ulonglong2* lp2 = (const ulonglong2*)&sh.lkb[wr][bl][0];
            #pragma unroll
            for (int i = 0; i < 12; i++) {
                ulonglong2 kv = kp2[i];
                ulonglong2 lv = lp2[i];
                wac[2*i]   = fma2(kv.x, cA, wac[2*i]);
                wac[2*i]   = fma2(lv.x, cB, wac[2*i]);
                wac[2*i+1] = fma2(kv.y, cA, wac[2*i+1]);
                wac[2*i+1] = fma2(lv.y, cB, wac[2*i+1]);
            }
            u64 kv = *(const u64*)&sh.kcb[wr][bl][48];
            u64 lv = *(const u64*)&sh.lkb[wr][bl][48];
            wac[24] = fma2(kv, cA, wac[24]);
            wac[24] = fma2(lv, cB, wac[24]);
        }
        // no barrier needed: all staging buffers are double-buffered

        odp += odS; ctp += ctS; otp += otS;
    }
}

extern "C" void kernel_launch(void* const* d_in, const int* in_sizes, int n_in,
                              void* d_out, int out_size)
{
    const float* odor  = (const float*)d_in[0];
    const float* ctx   = (const float*)d_in[1];
    const float* pn_w  = (const float*)d_in[2];
    const float* kn_b  = (const float*)d_in[3];
    const float* apl_w = (const float*)d_in[4];
    const float* apl_b = (const float*)d_in[5];
    const float* Wdm   = (const float*)d_in[6];
    const float* mb_b  = (const float*)d_in[7];
    const float* Wmd   = (const float*)d_in[8];
    const float* Wdd   = (const float*)d_in[9];
    const float* Wcd   = (const float*)d_in[10];
    const float* dan_b = (const float*)d_in[11];
    const float* decW  = (const float*)d_in[12];
    const float* decB  = (const float*)d_in[13];
    const float* kw0   = (const float*)d_in[14];
    const float* wa0   = (const float*)d_in[15];

    const int Bn = in_sizes[14] / (KN * MBN);   // kc_weight0 = B*50*10
    const int T  = in_sizes[0] / (Bn * 3);      // odor = T*B*3

    fly_kernel<<<Bn / BPC, NTHR>>>(odor, ctx, pn_w, kn_b, apl_w, apl_b,
                                   Wdm, mb_b, Wmd, Wdd, Wcd, dan_b,
                                   decW, decB, kw0, wa0,
                                   (float*)d_out, Bn, T);
}

// round 2
// speedup vs baseline: 1.3495x; 1.3495x over previous
#include <cuda_runtime.h>

#define MBN  10
#define WPC  5                 // warps per CTA
#define BPW  3                 // batches per warp (lanes 0..29 active)
#define BPC  (WPC*BPW)         // 15 batches per CTA
#define NTHR (32*WPC)          // 160 threads

typedef unsigned long long u64;

__device__ __forceinline__ u64 fma2(u64 a, u64 b, u64 c){
    u64 d; asm("fma.rn.f32x2 %0, %1, %2, %3;" : "=l"(d) : "l"(a), "l"(b), "l"(c)); return d;
}
__device__ __forceinline__ u64 add2(u64 a, u64 b){
    u64 d; asm("add.rn.f32x2 %0, %1, %2;" : "=l"(d) : "l"(a), "l"(b)); return d;
}
__device__ __forceinline__ u64 packs(float x){
    u64 r; asm("mov.b64 %0, {%1, %1};" : "=l"(r) : "f"(x)); return r;
}
__device__ __forceinline__ u64 packp(float lo, float hi){
    u64 r; asm("mov.b64 %0, {%1, %2};" : "=l"(r) : "f"(lo), "f"(hi)); return r;
}
__device__ __forceinline__ float hadd2(u64 v){
    float lo, hi; asm("mov.b64 {%0, %1}, %2;" : "=f"(lo), "=f"(hi) : "l"(v)); return lo + hi;
}

struct __align__(16) Sh {
    float part[16][MBN][12];   // [slot][j(k-group)][m]  kcv partials
    float psum[16][12];        // APL partials
    float dan[16][12];         // dan_n row (single buffered)
    float lowdan[16][12];      // low_dan_n row
    float mbon[16][12];        // mbon_n row
    float WdmT[MBN][12];       // [m][d] = mbon_dan_weight[d,m]
    float WddT[MBN][12];       // [m][j] = dan_dan_weight[j,m]
    float WmdT[MBN][12];       // [m][j] = dan_mbon_weight[j,m]
    float dec[2][12];
    float decb[2];
};

__global__ void __launch_bounds__(NTHR, 2) fly_kernel(
    const float* __restrict__ odor,  const float* __restrict__ ctx,
    const float* __restrict__ pn_w,  const float* __restrict__ kn_b,
    const float* __restrict__ apl_w, const float* __restrict__ apl_b,
    const float* __restrict__ Wdm,   const float* __restrict__ mb_b,
    const float* __restrict__ Wmd,   const float* __restrict__ Wdd,
    const float* __restrict__ Wcd,   const float* __restrict__ dan_b,
    const float* __restrict__ decW,  const float* __restrict__ decB,
    const float* __restrict__ kw0,   const float* __restrict__ wa0,
    float* __restrict__ out, int Bn, int T)
{
    __shared__ Sh sh;
    const int tid  = threadIdx.x;
    const int lane = tid & 31;
    const int warp = tid >> 5;
    const int m    = lane % MBN;              // m-column role AND k-group index
    const int blL  = lane / MBN;              // 0..2 real, 3 = idle lanes
    const int slot = (blL == 3) ? 15 : (warp * BPW + blL);
    const int b    = blockIdx.x * BPC + slot;
    const bool active = (blL < 3) && (b < Bn);
    const int bload = (b < Bn) ? b : (Bn - 1);
    const int k0   = m * 5;                   // owned KC rows

    // ---- shared init ----
    for (int i = tid; i < 16*12; i += NTHR) { sh.dan[0][i] = 0.f; sh.lowdan[0][i] = 0.f; }
    if (tid < 100) {
        int a = tid / 10, d = tid % 10;
        sh.WdmT[a][d] = Wdm[d*10 + a];
        sh.WddT[a][d] = Wdd[d*10 + a];
        sh.WmdT[a][d] = Wmd[d*10 + a];
    }
    if (tid < 20) sh.dec[tid/10][tid%10] = decW[tid];
    if (tid < 2)  sh.decb[tid] = decB[tid];

    // ---- per-thread constants ----
    float pw0[5], pw1[5], pw2[5], kb[5], aw[5];
    {
        const float* pwp = pn_w + (size_t)bload*150 + k0;
        #pragma unroll
        for (int j = 0; j < 5; j++) {
            pw0[j] = pwp[j]; pw1[j] = pwp[50+j]; pw2[j] = pwp[100+j];
            kb[j]  = kn_b[k0+j]; aw[j] = apl_w[k0+j];
        }
    }
    const float aplB = apl_b[0];
    const float mbB  = mb_b[m];
    const float wcm  = Wcd[m];
    const float dBm  = dan_b[m];

    // ---- plastic state: rows k0..k0+4, all m, packed over m-pairs ----
    // wac holds 0.25*wact
    u64 kcw[25], wac[25];
    {
        const float* kp = kw0 + (size_t)bload*500 + k0*10;
        const float* ap = wa0 + (size_t)bload*500 + k0*10;
        #pragma unroll
        for (int k = 0; k < 5; k++)
            #pragma unroll
            for (int mp = 0; mp < 5; mp++) {
                kcw[k*5+mp] = *(const u64*)(kp + k*10 + 2*mp);
                float2 w = *(const float2*)(ap + k*10 + 2*mp);
                wac[k*5+mp] = packp(0.25f*w.x, 0.25f*w.y);
            }
    }
    __syncthreads();

    // ---- recurrent state ----
    float kcs[5] = {0,0,0,0,0}, lks[5] = {0,0,0,0,0};
    float kcp[5] = {0,0,0,0,0}, lkp[5] = {0,0,0,0,0};   // 0.125*kc_prev, -0.125*lk_prev
    float apl = 0.f, mbon = 0.f, danm = 0.f, lowdan = 0.f;

    const float ALPHA = 0.5f/5.5f;
    const float OMA   = 1.0f - 0.5f/5.5f;
    const u64   C75   = packs(0.75f);

    float*       partW  = &sh.part[slot][m][0];
    const float* partR  = &sh.part[slot][0][m];
    float*       psumR  = &sh.psum[slot][0];
    float*       danR   = &sh.dan[slot][0];
    float*       ldR    = &sh.lowdan[slot][0];
    float*       mbR    = &sh.mbon[slot][0];
    const float* wdmR   = &sh.WdmT[m][0];
    const float* wddR   = &sh.WddT[m][0];
    const float* wmdR   = &sh.WmdT[m][0];
    const float* decR   = &sh.dec[(m < 2) ? m : 0][0];

    const float* odp = odor + (size_t)bload*3;
    const float* ctp = ctx  + bload;
    float*       otp = out  + (size_t)b*2 + m;
    const size_t odS = (size_t)Bn*3, ctS = (size_t)Bn, otS = (size_t)Bn*2;

    for (int t = 0; t < T; t++) {
        // ===== Phase A: Kenyon + low-pass + kcv partials (own 5 k's) =====
        float o0 = odp[0], o1 = odp[1], o2 = odp[2];
        float cx = ctp[0];
        float psum = 0.f;
        #pragma unroll
        for (int j = 0; j < 5; j++) {
            float pn  = fmaf(o0, pw0[j], fmaf(o1, pw1[j], o2*pw2[j]));
            float r   = fmaxf(pn - apl + kb[j], 0.f);
            float kcn = fmaf(0.5f, r, 0.5f*kcs[j]);
            kcs[j] = kcn;
            lks[j] = fmaf(ALPHA, kcn, OMA*lks[j]);
            psum   = fmaf(kcn, aw[j], psum);
        }
        psumR[m] = psum;
        {
            u64 acc0=0, acc1=0, acc2=0, acc3=0, acc4=0;
            #pragma unroll
            for (int k = 0; k < 5; k++) {
                u64 pk = packs(kcs[k]);
                acc0 = fma2(pk, kcw[k*5+0], acc0);
                acc1 = fma2(pk, kcw[k*5+1], acc1);
                acc2 = fma2(pk, kcw[k*5+2], acc2);
                acc3 = fma2(pk, kcw[k*5+3], acc3);
                acc4 = fma2(pk, kcw[k*5+4], acc4);
            }
            *(u64*)(partW+0) = acc0; *(u64*)(partW+2) = acc1;
            *(u64*)(partW+4) = acc2; *(u64*)(partW+6) = acc3;
            *(u64*)(partW+8) = acc4;
        }
        __syncwarp();

        // ===== Phase B: APL, dmod, kcv, plasticity(t-1), decay =====
        {   // APL (pairwise)
            u64 s = add2(add2(*(const u64*)(psumR+0), *(const u64*)(psumR+2)),
                         add2(*(const u64*)(psumR+4), *(const u64*)(psumR+6)));
            s = add2(s, *(const u64*)(psumR+8));
            apl = fmaf(0.5f, fmaxf(hadd2(s) + aplB, 0.f), 0.5f*apl);
        }
        u64 ddp[5], ldp[5];
        #pragma unroll
        for (int p = 0; p < 5; p++) {
            ddp[p] = *(const u64*)(danR + 2*p);
            ldp[p] = *(const u64*)(ldR  + 2*p);
        }
        float dmod;
        {
            u64 a2 = 0;
            #pragma unroll
            for (int p = 0; p < 5; p++) a2 = fma2(ddp[p], *(const u64*)(wdmR+2*p), a2);
            dmod = 1.f / (1.f + __expf(-hadd2(a2)));
        }
        float kcv;
        {
            float pv[10];
            #pragma unroll
            for (int jj = 0; jj < 10; jj++) pv[jj] = partR[jj*12];
            kcv = ((pv[0]+pv[1]) + (pv[2]+pv[3]))
                + (((pv[4]+pv[5]) + (pv[6]+pv[7])) + (pv[8]+pv[9]));
        }
        // plasticity from step t-1:  wac += 0.125*kc_prev*lowdan_prev - 0.125*lk_prev*dan_prev
        #pragma unroll
        for (int k = 0; k < 5; k++) {
            u64 ka = packs(kcp[k]);
            u64 kb2 = packs(lkp[k]);
            #pragma unroll
            for (int mp = 0; mp < 5; mp++) {
                u64 w = wac[k*5+mp];
                w = fma2(ka,  ldp[mp], w);
                w = fma2(kb2, ddp[mp], w);
                wac[k*5+mp] = w;
            }
        }
        // decay: kc_w <- 0.75*kc_w + 0.25*wact
        #pragma unroll
        for (int i = 0; i < 25; i++) kcw[i] = fma2(kcw[i], C75, wac[i]);

        mbon = fmaf(0.5f*dmod, fmaxf(kcv + mbB, 0.f), 0.5f*mbon);
        mbR[m] = mbon;
        __syncwarp();

        // ===== Phase C: DAN, traces, decoder =====
        u64 mbp[5];
        #pragma unroll
        for (int p = 0; p < 5; p++) mbp[p] = *(const u64*)(mbR + 2*p);
        {
            u64 c2 = 0;
            #pragma unroll
            for (int p = 0; p < 5; p++) {
                c2 = fma2(ddp[p], *(const u64*)(wddR+2*p), c2);
                c2 = fma2(mbp[p], *(const u64*)(wmdR+2*p), c2);
            }
            float dp = hadd2(c2) + fmaf(cx, wcm, dBm);
            danm = fmaf(0.5f, fmaxf(dp, 0.f), 0.5f*danm);
        }
        danR[m] = danm;
        lowdan  = fmaf(ALPHA, danm, OMA*lowdan);
        ldR[m]  = lowdan;
        #pragma unroll
        for (int k = 0; k < 5; k++) { kcp[k] = 0.125f*kcs[k]; lkp[k] = -0.125f*lks[k]; }

        if (active && m < 2) {
            u64 d2 = 0;
            #pragma unroll
            for (int p = 0; p < 5; p++) d2 = fma2(mbp[p], *(const u64*)(decR+2*p), d2);
            otp[0] = hadd2(d2) + sh.decb[m];
        }

        odp += odS; ctp += ctS; otp += otS;
    }
}

extern "C" void kernel_launch(void* const* d_in, const int* in_sizes, int n_in,
                              void* d_out, int out_size)
{
    const float* odor  = (const float*)d_in[0];
    const float* ctx   = (const float*)d_in[1];
    const float* pn_w  = (const float*)d_in[2];
    const float* kn_b  = (const float*)d_in[3];
    const float* apl_w = (const float*)d_in[4];
    const float* apl_b = (const float*)d_in[5];
    const float* Wdm   = (const float*)d_in[6];
    const float* mb_b  = (const float*)d_in[7];
    const float* Wmd   = (const float*)d_in[8];
    const float* Wdd   = (const float*)d_in[9];
    const float* Wcd   = (const float*)d_in[10];
    const float* dan_b = (const float*)d_in[11];
    const float* decW  = (const float*)d_in[12];
    const float* decB  = (const float*)d_in[13];
    const float* kw0   = (const float*)d_in[14];
    const float* wa0   = (const float*)d_in[15];

    const int Bn = in_sizes[14] / 500;          // kc_weight0 = B*50*10
    const int T  = in_sizes[0] / (Bn * 3);      // odor = T*B*3

    const int grid = (Bn + BPC - 1) / BPC;
    fly_kernel<<<grid, NTHR>>>(odor, ctx, pn_w, kn_b, apl_w, apl_b,
                               Wdm, mb_b, Wmd, Wdd, Wcd, dan_b,
                               decW, decB, kw0, wa0,
                               (float*)d_out, Bn, T);
}